// round 1
// baseline (speedup 1.0000x reference)
#include <cuda_runtime.h>

#define B_   32
#define N_   1024
#define DIM_ 1152
#define H_   12
#define KV_  4
#define D_   96

// ---------------- scratch (device globals; no allocations) ----------------
__device__ float g_q[37748736];    // [B,N,1152]  q projection
__device__ float g_kvp[25165824];  // [B,N,768]   k (cols 0..383) | v (cols 384..767)
__device__ float g_pre[37748736];  // [B,N,1152]  attn*scale + dwc, pre-projection
__device__ float g_dwc[12582912];  // [B,N,384]   depthwise conv of v
__device__ float g_kv[1179648];    // [B,KV,96,96]
__device__ float g_sq[384];        // scale per (b,h)
__device__ float g_sk[128];        // scale per (b,kv)

// ---------------- SGEMM: C[M,N] = A[M,K] @ W[K,N] + bias ----------------
#define BM 128
#define BN 128
#define BK 8
#define TM 8
#define TN 8

__global__ __launch_bounds__(256, 2) void sgemm_bias(
    const float* __restrict__ A, const float* __restrict__ W,
    const float* __restrict__ bias, float* __restrict__ C,
    int M, int N, int K)
{
    __shared__ float As[BK][BM];
    __shared__ float Bs[BK][BN];
    const int tid = threadIdx.x;
    const int tr  = tid >> 4;        // 0..15
    const int tc  = tid & 15;        // 0..15
    const int aRow = tid >> 1;       // 0..127
    const int aCol = (tid & 1) << 2; // 0 or 4
    const int bRow = tid >> 5;       // 0..7
    const int bCol = (tid & 31) << 2;

    const float* Ab = A + (size_t)blockIdx.y * BM * K;
    const float* Wb = W + (size_t)blockIdx.x * BN;

    float acc[TM][TN];
    #pragma unroll
    for (int i = 0; i < TM; i++)
        #pragma unroll
        for (int j = 0; j < TN; j++) acc[i][j] = 0.f;

    for (int k0 = 0; k0 < K; k0 += BK) {
        float4 a4 = *(const float4*)(Ab + (size_t)aRow * K + k0 + aCol);
        As[aCol + 0][aRow] = a4.x;
        As[aCol + 1][aRow] = a4.y;
        As[aCol + 2][aRow] = a4.z;
        As[aCol + 3][aRow] = a4.w;
        *(float4*)&Bs[bRow][bCol] =
            *(const float4*)(Wb + (size_t)(k0 + bRow) * N + bCol);
        __syncthreads();
        #pragma unroll
        for (int kk = 0; kk < BK; kk++) {
            float regM[TM], regN[TN];
            *(float4*)&regM[0] = *(const float4*)&As[kk][tr * TM];
            *(float4*)&regM[4] = *(const float4*)&As[kk][tr * TM + 4];
            *(float4*)&regN[0] = *(const float4*)&Bs[kk][tc * TN];
            *(float4*)&regN[4] = *(const float4*)&Bs[kk][tc * TN + 4];
            #pragma unroll
            for (int i = 0; i < TM; i++)
                #pragma unroll
                for (int j = 0; j < TN; j++)
                    acc[i][j] = fmaf(regM[i], regN[j], acc[i][j]);
        }
        __syncthreads();
    }

    const int row0 = blockIdx.y * BM + tr * TM;
    const int col0 = blockIdx.x * BN + tc * TN;
    float bj[TN];
    #pragma unroll
    for (int j = 0; j < TN; j++) bj[j] = bias[col0 + j];
    #pragma unroll
    for (int i = 0; i < TM; i++) {
        #pragma unroll
        for (int j = 0; j < TN; j += 4) {
            float4 o;
            o.x = acc[i][j + 0] + bj[j + 0];
            o.y = acc[i][j + 1] + bj[j + 1];
            o.z = acc[i][j + 2] + bj[j + 2];
            o.w = acc[i][j + 3] + bj[j + 3];
            *(float4*)(C + (size_t)(row0 + i) * N + col0 + j) = o;
        }
    }
}

// ---------------- focus norms: scale = ||relu(t)|| / ||relu(t)^3|| --------
// which==0: q buffer (ld=1152, 12 heads)   which==1: k half of kvp (ld=768, 4 heads)
__global__ void norm_kernel(int which)
{
    const int nh = which ? KV_ : H_;
    const int ld = which ? 768 : DIM_;
    const float* src = which ? g_kvp : g_q;
    const int b  = blockIdx.x / nh;
    const int hh = blockIdx.x - b * nh;
    const float* base = src + (size_t)b * N_ * ld + hh * D_;

    float s2 = 0.f, s6 = 0.f;
    for (int i = threadIdx.x; i < N_ * D_; i += blockDim.x) {
        int n = i / D_;
        int d = i - n * D_;
        float v = base[(size_t)n * ld + d];
        v = fmaxf(v, 0.f);
        float v2 = v * v;
        float v3 = v2 * v;
        s2 += v2;
        s6 += v3 * v3;
    }
    __shared__ float r2[256], r6[256];
    r2[threadIdx.x] = s2;
    r6[threadIdx.x] = s6;
    __syncthreads();
    for (int s = 128; s > 0; s >>= 1) {
        if (threadIdx.x < s) {
            r2[threadIdx.x] += r2[threadIdx.x + s];
            r6[threadIdx.x] += r6[threadIdx.x + s];
        }
        __syncthreads();
    }
    if (threadIdx.x == 0) {
        float sc = (r6[0] > 0.f) ? sqrtf(r2[0] / r6[0]) : 0.f;
        (which ? g_sk : g_sq)[blockIdx.x] = sc;
    }
}

// ---------------- kv[d,e] = sum_n relu(k[n,d])^3 * v[n,e]  (unscaled) -----
__global__ __launch_bounds__(256) void kv_gemm_kernel()
{
    const int b = blockIdx.x >> 2;
    const int g = blockIdx.x & 3;
    __shared__ float ks[32 * 96];
    __shared__ float vs[32 * 96];
    const int tid = threadIdx.x;
    const int ty = tid >> 4, tx = tid & 15;

    float acc[6][6];
    #pragma unroll
    for (int i = 0; i < 6; i++)
        #pragma unroll
        for (int j = 0; j < 6; j++) acc[i][j] = 0.f;

    const float* kbase = g_kvp + (size_t)b * N_ * 768 + g * D_;
    const float* vbase = kbase + 384;

    for (int t0 = 0; t0 < N_; t0 += 32) {
        for (int i = tid; i < 32 * 96; i += 256) {
            int r = i / 96;
            int c = i - r * 96;
            size_t off = (size_t)(t0 + r) * 768 + c;
            float kl = fmaxf(kbase[off], 0.f);
            ks[i] = kl * kl * kl;
            vs[i] = vbase[off];
        }
        __syncthreads();
        #pragma unroll 8
        for (int kk = 0; kk < 32; kk++) {
            float rk[6], rv[6];
            #pragma unroll
            for (int i = 0; i < 6; i++) rk[i] = ks[kk * 96 + ty * 6 + i];
            #pragma unroll
            for (int j = 0; j < 6; j++) rv[j] = vs[kk * 96 + tx * 6 + j];
            #pragma unroll
            for (int i = 0; i < 6; i++)
                #pragma unroll
                for (int j = 0; j < 6; j++)
                    acc[i][j] = fmaf(rk[i], rv[j], acc[i][j]);
        }
        __syncthreads();
    }
    float* dst = g_kv + (size_t)blockIdx.x * 96 * 96;
    #pragma unroll
    for (int i = 0; i < 6; i++)
        #pragma unroll
        for (int j = 0; j < 6; j++)
            dst[(ty * 6 + i) * 96 + tx * 6 + j] = acc[i][j];
}

// ---------------- depthwise 3x3 conv on v over 32x32 latent grid ----------
__global__ __launch_bounds__(384) void dwc_kernel(const float* __restrict__ w,
                                                  const float* __restrict__ bia)
{
    const int y = blockIdx.x;   // row on latent grid
    const int b = blockIdx.y;
    const int c = threadIdx.x;  // channel 0..383 (kv*96+d)

    float wr[9];
    #pragma unroll
    for (int i = 0; i < 9; i++) wr[i] = w[c * 9 + i];
    const float bv = bia[c];

    const float* base = g_kvp + (size_t)b * N_ * 768 + 384 + c;
    const float* r0 = base + (size_t)(y * 32) * 768;
    const float* rm = r0 - (size_t)32 * 768;
    const float* rp = r0 + (size_t)32 * 768;
    const bool vm = (y > 0), vp = (y < 31);

    float A0 = 0.f, A1 = 0.f, A2 = 0.f;   // column x-1 (rows y-1, y, y+1)
    float Bc0, Bc1, Bc2;                  // column x
    float Cc0, Cc1, Cc2;                  // column x+1
    Bc0 = vm ? rm[0] : 0.f;
    Bc1 = r0[0];
    Bc2 = vp ? rp[0] : 0.f;

    float* out = g_dwc + (size_t)(b * N_ + y * 32) * 384 + c;
    for (int x = 0; x < 32; x++) {
        if (x < 31) {
            size_t o = (size_t)(x + 1) * 768;
            Cc0 = vm ? rm[o] : 0.f;
            Cc1 = r0[o];
            Cc2 = vp ? rp[o] : 0.f;
        } else {
            Cc0 = Cc1 = Cc2 = 0.f;
        }
        float o = bv;
        o = fmaf(A0, wr[0], o); o = fmaf(Bc0, wr[1], o); o = fmaf(Cc0, wr[2], o);
        o = fmaf(A1, wr[3], o); o = fmaf(Bc1, wr[4], o); o = fmaf(Cc1, wr[5], o);
        o = fmaf(A2, wr[6], o); o = fmaf(Bc2, wr[7], o); o = fmaf(Cc2, wr[8], o);
        out[(size_t)x * 384] = o;
        A0 = Bc0; A1 = Bc1; A2 = Bc2;
        Bc0 = Cc0; Bc1 = Cc1; Bc2 = Cc2;
    }
}

// ------- attn[n,e] = s_q*s_k * sum_d relu(q[n,d])^3 * kv[d,e]  + dwc ------
__global__ __launch_bounds__(256) void attn_kernel()
{
    __shared__ float kvs[96 * 96];  // 36 KB
    __shared__ float qs[32 * 96];   // 12 KB
    const int bh = blockIdx.y;
    const int b = bh / H_;
    const int h = bh - b * H_;
    const int g = h & 3;            // h % KV
    const int n0 = blockIdx.x * 32;
    const int tid = threadIdx.x;

    const float* kvsrc = g_kv + (size_t)(b * KV_ + g) * 9216;
    for (int i = tid; i < 9216; i += 256) kvs[i] = kvsrc[i];

    const float* qsrc = g_q + (size_t)(b * N_ + n0) * DIM_ + h * D_;
    for (int i = tid; i < 3072; i += 256) {
        int r = i / 96;
        int d = i - r * 96;
        float v = fmaxf(qsrc[(size_t)r * DIM_ + d], 0.f);
        qs[i] = v * v * v;
    }
    __syncthreads();

    const int ty = tid >> 4, tx = tid & 15;   // 16x16; 2 rows x 6 cols per thread
    float acc[2][6];
    #pragma unroll
    for (int i = 0; i < 2; i++)
        #pragma unroll
        for (int j = 0; j < 6; j++) acc[i][j] = 0.f;

    #pragma unroll 4
    for (int k = 0; k < 96; k++) {
        float q0 = qs[(ty * 2 + 0) * 96 + k];
        float q1 = qs[(ty * 2 + 1) * 96 + k];
        float rv[6];
        #pragma unroll
        for (int j = 0; j < 6; j++) rv[j] = kvs[k * 96 + tx * 6 + j];
        #pragma unroll
        for (int j = 0; j < 6; j++) {
            acc[0][j] = fmaf(q0, rv[j], acc[0][j]);
            acc[1][j] = fmaf(q1, rv[j], acc[1][j]);
        }
    }

    const float scale = g_sq[bh] * g_sk[b * KV_ + g];
    const float* dsrc = g_dwc + (size_t)(b * N_ + n0) * 384 + g * D_;
    float* dst = g_pre + (size_t)(b * N_ + n0) * DIM_ + h * D_;
    #pragma unroll
    for (int i = 0; i < 2; i++) {
        int r = ty * 2 + i;
        #pragma unroll
        for (int j = 0; j < 6; j++) {
            int e = tx * 6 + j;
            dst[(size_t)r * DIM_ + e] =
                acc[i][j] * scale + dsrc[(size_t)r * 384 + e];
        }
    }
}

// ---------------- launch ----------------
extern "C" void kernel_launch(void* const* d_in, const int* in_sizes, int n_in,
                              void* d_out, int out_size)
{
    const float* x      = (const float*)d_in[0];
    const float* wq_w   = (const float*)d_in[1];
    const float* wq_b   = (const float*)d_in[2];
    const float* wkv_w  = (const float*)d_in[3];
    const float* wkv_b  = (const float*)d_in[4];
    const float* dwc_w  = (const float*)d_in[5];
    const float* dwc_b  = (const float*)d_in[6];
    const float* proj_w = (const float*)d_in[7];
    const float* proj_b = (const float*)d_in[8];
    float* out = (float*)d_out;

    float *gq = nullptr, *gkvp = nullptr, *gpre = nullptr;
    cudaGetSymbolAddress((void**)&gq,   g_q);
    cudaGetSymbolAddress((void**)&gkvp, g_kvp);
    cudaGetSymbolAddress((void**)&gpre, g_pre);

    const int M = B_ * N_;

    sgemm_bias<<<dim3(DIM_ / BN, M / BM), 256>>>(x, wq_w, wq_b, gq, M, DIM_, DIM_);
    sgemm_bias<<<dim3(768  / BN, M / BM), 256>>>(x, wkv_w, wkv_b, gkvp, M, 768, DIM_);
    norm_kernel<<<B_ * H_,  256>>>(0);
    norm_kernel<<<B_ * KV_, 256>>>(1);
    kv_gemm_kernel<<<B_ * KV_, 256>>>();
    dwc_kernel<<<dim3(32, B_), 384>>>(dwc_w, dwc_b);
    attn_kernel<<<dim3(32, B_ * H_), 256>>>();
    sgemm_bias<<<dim3(DIM_ / BN, M / BM), 256>>>(gpre, proj_w, proj_b, out, M, DIM_, DIM_);
}

// round 3
// speedup vs baseline: 1.6761x; 1.6761x over previous
#include <cuda_runtime.h>
#include <cstdint>

#define B_   32
#define N_   1024
#define DIM_ 1152
#define H_   12
#define KV_  4
#define D_   96

// ---------------- scratch (device globals; no allocations) ----------------
__device__ float g_q[37748736];    // [B,N,1152]
__device__ float g_kvp[25165824];  // [B,N,768] k | v
__device__ float g_pre[37748736];  // [B,N,1152]
__device__ float g_dwc[12582912];  // [B,N,384]
__device__ float g_kv[1179648];    // [B,KV,96,96]
__device__ float g_nq[768];        // (s2,s6) per (b,h)
__device__ float g_nk[256];        // (s2,s6) per (b,kv)

// ---------------- async copy + mma helpers ----------------
__device__ __forceinline__ void cp16(uint32_t dst, const void* src) {
    asm volatile("cp.async.ca.shared.global [%0], [%1], 16;" :: "r"(dst), "l"(src));
}
__device__ __forceinline__ void cp_commit() { asm volatile("cp.async.commit_group;"); }
template<int W> __device__ __forceinline__ void cp_wait() {
    asm volatile("cp.async.wait_group %0;" :: "n"(W));
}
__device__ __forceinline__ void mma8(float* c, const uint32_t* a, const uint32_t* b) {
    asm volatile(
        "mma.sync.aligned.m16n8k8.row.col.f32.tf32.tf32.f32 "
        "{%0,%1,%2,%3},{%4,%5,%6,%7},{%8,%9},{%0,%1,%2,%3};"
        : "+f"(c[0]), "+f"(c[1]), "+f"(c[2]), "+f"(c[3])
        : "r"(a[0]), "r"(a[1]), "r"(a[2]), "r"(a[3]), "r"(b[0]), "r"(b[1]));
}
__device__ __forceinline__ uint32_t f2tf(float x) {
    uint32_t r;
    asm("cvt.rna.tf32.f32 %0, %1;" : "=r"(r) : "f"(x));
    return r;
}

#define ASTR 20
#define BSTR 136

// ---- tf32 tensor-core GEMM: C[M,N] = A[M,K] @ W[K,N] + bias --------------
// MODE 0: single-pass tf32 (RN).  MODE 1: 3xTF32 error-compensated (~fp32).
template<int MODE>
__global__ __launch_bounds__(256) void tf32_gemm_bias(
    const float* __restrict__ A, const float* __restrict__ W,
    const float* __restrict__ bias, float* __restrict__ C,
    int M, int N, int K)
{
    __shared__ float smA[2][128 * ASTR];  // [m][k] fp32
    __shared__ float smB[2][16 * BSTR];   // [k][n] fp32

    const int tid  = threadIdx.x;
    const int lane = tid & 31, warp = tid >> 5;
    const int wm = warp >> 2, wn = warp & 3;   // 2 x 4 warp grid
    const int gid = lane >> 2, tig = lane & 3;

    const float* Ab = A + (size_t)blockIdx.y * 128 * K;
    const float* Wb = W + blockIdx.x * 128;

    const int ar0 = tid >> 2,          ac0 = (tid & 3) << 2;
    const int ar1 = (tid + 256) >> 2;
    const int br0 = tid >> 5,          bc0 = (tid & 31) << 2;
    const int br1 = (tid + 256) >> 5;

    const uint32_t aB[2] = { (uint32_t)__cvta_generic_to_shared(&smA[0][0]),
                             (uint32_t)__cvta_generic_to_shared(&smA[1][0]) };
    const uint32_t bB[2] = { (uint32_t)__cvta_generic_to_shared(&smB[0][0]),
                             (uint32_t)__cvta_generic_to_shared(&smB[1][0]) };

    float acc[4][4][4];
    #pragma unroll
    for (int i = 0; i < 4; i++)
        #pragma unroll
        for (int j = 0; j < 4; j++)
            #pragma unroll
            for (int r = 0; r < 4; r++) acc[i][j][r] = 0.f;

    auto load_tile = [&](int k0, int buf) {
        cp16(aB[buf] + (ar0 * ASTR + ac0) * 4, Ab + (size_t)ar0 * K + k0 + ac0);
        cp16(aB[buf] + (ar1 * ASTR + ac0) * 4, Ab + (size_t)ar1 * K + k0 + ac0);
        cp16(bB[buf] + (br0 * BSTR + bc0) * 4, Wb + (size_t)(k0 + br0) * N + bc0);
        cp16(bB[buf] + (br1 * BSTR + bc0) * 4, Wb + (size_t)(k0 + br1) * N + bc0);
        cp_commit();
    };

    const int T = K / 16;
    load_tile(0, 0);

    for (int t = 0; t < T; t++) {
        if (t + 1 < T) {
            load_tile((t + 1) * 16, (t + 1) & 1);
            cp_wait<1>();
        } else {
            cp_wait<0>();
        }
        __syncthreads();

        const float* As = smA[t & 1];
        const float* Bs = smB[t & 1];
        #pragma unroll
        for (int ks = 0; ks < 2; ks++) {
            uint32_t ah[4][4], al[4][4], bh[4][2], bl[4][2];
            #pragma unroll
            for (int ti = 0; ti < 4; ti++) {
                int m0 = wm * 64 + ti * 16 + gid;
                int kk = ks * 8 + tig;
                float v0 = As[m0 * ASTR + kk];
                float v1 = As[(m0 + 8) * ASTR + kk];
                float v2 = As[m0 * ASTR + kk + 4];
                float v3 = As[(m0 + 8) * ASTR + kk + 4];
                ah[ti][0] = f2tf(v0); ah[ti][1] = f2tf(v1);
                ah[ti][2] = f2tf(v2); ah[ti][3] = f2tf(v3);
                if (MODE == 1) {
                    al[ti][0] = f2tf(v0 - __uint_as_float(ah[ti][0]));
                    al[ti][1] = f2tf(v1 - __uint_as_float(ah[ti][1]));
                    al[ti][2] = f2tf(v2 - __uint_as_float(ah[ti][2]));
                    al[ti][3] = f2tf(v3 - __uint_as_float(ah[ti][3]));
                }
            }
            #pragma unroll
            for (int tj = 0; tj < 4; tj++) {
                int n0 = wn * 32 + tj * 8 + gid;
                float v0 = Bs[(ks * 8 + tig) * BSTR + n0];
                float v1 = Bs[(ks * 8 + tig + 4) * BSTR + n0];
                bh[tj][0] = f2tf(v0); bh[tj][1] = f2tf(v1);
                if (MODE == 1) {
                    bl[tj][0] = f2tf(v0 - __uint_as_float(bh[tj][0]));
                    bl[tj][1] = f2tf(v1 - __uint_as_float(bh[tj][1]));
                }
            }
            #pragma unroll
            for (int ti = 0; ti < 4; ti++)
                #pragma unroll
                for (int tj = 0; tj < 4; tj++) {
                    if (MODE == 1) {
                        mma8(acc[ti][tj], al[ti], bh[tj]);
                        mma8(acc[ti][tj], ah[ti], bl[tj]);
                    }
                    mma8(acc[ti][tj], ah[ti], bh[tj]);
                }
        }
        __syncthreads();
    }

    #pragma unroll
    for (int ti = 0; ti < 4; ti++) {
        #pragma unroll
        for (int tj = 0; tj < 4; tj++) {
            int row = blockIdx.y * 128 + wm * 64 + ti * 16 + gid;
            int col = blockIdx.x * 128 + wn * 32 + tj * 8 + tig * 2;
            float b0 = bias[col], b1 = bias[col + 1];
            float2 v0 = { acc[ti][tj][0] + b0, acc[ti][tj][1] + b1 };
            float2 v1 = { acc[ti][tj][2] + b0, acc[ti][tj][3] + b1 };
            *(float2*)(C + (size_t)row * N + col) = v0;
            *(float2*)(C + (size_t)(row + 8) * N + col) = v1;
        }
    }
}

// ---- focus norm partials: atomic (sum relu^2, sum relu^6) per (b,head) ---
__global__ void norm_kernel(int which)
{
    const int nh = which ? KV_ : H_;
    const int ld = which ? 768 : DIM_;
    const float* src = which ? g_kvp : g_q;
    float* acc = which ? g_nk : g_nq;
    const int bh = blockIdx.x;
    const int b = bh / nh, hh = bh - b * nh;
    const float* base = src + (size_t)b * N_ * ld + hh * D_
                            + (size_t)blockIdx.y * 128 * ld;

    float s2 = 0.f, s6 = 0.f;
    int n = threadIdx.x / 96, d = threadIdx.x % 96;
    for (int i = threadIdx.x; i < 128 * 96; i += 256) {
        float v = fmaxf(base[(size_t)n * ld + d], 0.f);
        float v2 = v * v, v3 = v2 * v;
        s2 += v2;
        s6 += v3 * v3;
        d += 64; n += 2;
        if (d >= 96) { d -= 96; n++; }
    }
    #pragma unroll
    for (int off = 16; off; off >>= 1) {
        s2 += __shfl_xor_sync(0xffffffffu, s2, off);
        s6 += __shfl_xor_sync(0xffffffffu, s6, off);
    }
    __shared__ float w2[8], w6[8];
    const int lane = threadIdx.x & 31, warp = threadIdx.x >> 5;
    if (lane == 0) { w2[warp] = s2; w6[warp] = s6; }
    __syncthreads();
    if (threadIdx.x == 0) {
        float t2 = 0.f, t6 = 0.f;
        #pragma unroll
        for (int i = 0; i < 8; i++) { t2 += w2[i]; t6 += w6[i]; }
        atomicAdd(&acc[bh * 2], t2);
        atomicAdd(&acc[bh * 2 + 1], t6);
    }
}

// ---- kv[d,e] += sum_n relu(k[n,d])^3 * v[n,e]  (chunked, atomic) ---------
__global__ __launch_bounds__(256) void kv_gemm_kernel()
{
    const int b = blockIdx.x >> 2;
    const int g = blockIdx.x & 3;
    __shared__ float ks[32 * 96];
    __shared__ float vs[32 * 96];
    const int tid = threadIdx.x;
    const int ty = tid >> 4, tx = tid & 15;

    float acc[6][6];
    #pragma unroll
    for (int i = 0; i < 6; i++)
        #pragma unroll
        for (int j = 0; j < 6; j++) acc[i][j] = 0.f;

    const float* kbase = g_kvp + (size_t)b * N_ * 768 + g * D_;
    const float* vbase = kbase + 384;
    const int t0b = blockIdx.y * 128;

    for (int t0 = t0b; t0 < t0b + 128; t0 += 32) {
        for (int i = tid; i < 32 * 96; i += 256) {
            int r = i / 96;
            int c = i - r * 96;
            size_t off = (size_t)(t0 + r) * 768 + c;
            float kl = fmaxf(kbase[off], 0.f);
            ks[i] = kl * kl * kl;
            vs[i] = vbase[off];
        }
        __syncthreads();
        #pragma unroll 8
        for (int kk = 0; kk < 32; kk++) {
            float rk[6], rv[6];
            #pragma unroll
            for (int i = 0; i < 6; i++) rk[i] = ks[kk * 96 + ty * 6 + i];
            #pragma unroll
            for (int j = 0; j < 6; j++) rv[j] = vs[kk * 96 + tx * 6 + j];
            #pragma unroll
            for (int i = 0; i < 6; i++)
                #pragma unroll
                for (int j = 0; j < 6; j++)
                    acc[i][j] = fmaf(rk[i], rv[j], acc[i][j]);
        }
        __syncthreads();
    }
    float* dst = g_kv + (size_t)blockIdx.x * 96 * 96;
    #pragma unroll
    for (int i = 0; i < 6; i++)
        #pragma unroll
        for (int j = 0; j < 6; j++)
            atomicAdd(&dst[(ty * 6 + i) * 96 + tx * 6 + j], acc[i][j]);
}

// ---- depthwise 3x3 conv on v over 32x32 latent grid ----------------------
__global__ __launch_bounds__(384) void dwc_kernel(const float* __restrict__ w,
                                                  const float* __restrict__ bia)
{
    const int y = blockIdx.x;
    const int b = blockIdx.y;
    const int c = threadIdx.x;

    float wr[9];
    #pragma unroll
    for (int i = 0; i < 9; i++) wr[i] = w[c * 9 + i];
    const float bv = bia[c];

    const float* base = g_kvp + (size_t)b * N_ * 768 + 384 + c;
    const float* r0 = base + (size_t)(y * 32) * 768;
    const float* rm = r0 - (size_t)32 * 768;
    const float* rp = r0 + (size_t)32 * 768;
    const bool vm = (y > 0), vp = (y < 31);

    float A0 = 0.f, A1 = 0.f, A2 = 0.f;
    float Bc0, Bc1, Bc2, Cc0, Cc1, Cc2;
    Bc0 = vm ? rm[0] : 0.f;
    Bc1 = r0[0];
    Bc2 = vp ? rp[0] : 0.f;

    float* out = g_dwc + (size_t)(b * N_ + y * 32) * 384 + c;
    for (int x = 0; x < 32; x++) {
        if (x < 31) {
            size_t o = (size_t)(x + 1) * 768;
            Cc0 = vm ? rm[o] : 0.f;
            Cc1 = r0[o];
            Cc2 = vp ? rp[o] : 0.f;
        } else {
            Cc0 = Cc1 = Cc2 = 0.f;
        }
        float o = bv;
        o = fmaf(A0, wr[0], o); o = fmaf(Bc0, wr[1], o); o = fmaf(Cc0, wr[2], o);
        o = fmaf(A1, wr[3], o); o = fmaf(Bc1, wr[4], o); o = fmaf(Cc1, wr[5], o);
        o = fmaf(A2, wr[6], o); o = fmaf(Bc2, wr[7], o); o = fmaf(Cc2, wr[8], o);
        out[(size_t)x * 384] = o;
        A0 = Bc0; A1 = Bc1; A2 = Bc2;
        Bc0 = Cc0; Bc1 = Cc1; Bc2 = Cc2;
    }
}

// ---- attn + scale + dwc fuse --------------------------------------------
__global__ __launch_bounds__(256) void attn_kernel()
{
    __shared__ float kvs[96 * 96];
    __shared__ float qs[32 * 96];
    const int bh = blockIdx.y;
    const int b = bh / H_;
    const int h = bh - b * H_;
    const int g = h & 3;
    const int n0 = blockIdx.x * 32;
    const int tid = threadIdx.x;

    const float* kvsrc = g_kv + (size_t)(b * KV_ + g) * 9216;
    for (int i = tid; i < 9216; i += 256) kvs[i] = kvsrc[i];

    const float* qsrc = g_q + (size_t)(b * N_ + n0) * DIM_ + h * D_;
    for (int i = tid; i < 3072; i += 256) {
        int r = i / 96;
        int d = i - r * 96;
        float v = fmaxf(qsrc[(size_t)r * DIM_ + d], 0.f);
        qs[i] = v * v * v;
    }
    __syncthreads();

    const int ty = tid >> 4, tx = tid & 15;
    float acc[2][6];
    #pragma unroll
    for (int i = 0; i < 2; i++)
        #pragma unroll
        for (int j = 0; j < 6; j++) acc[i][j] = 0.f;

    #pragma unroll 4
    for (int k = 0; k < 96; k++) {
        float q0 = qs[(ty * 2 + 0) * 96 + k];
        float q1 = qs[(ty * 2 + 1) * 96 + k];
        float rv[6];
        #pragma unroll
        for (int j = 0; j < 6; j++) rv[j] = kvs[k * 96 + tx * 6 + j];
        #pragma unroll
        for (int j = 0; j < 6; j++) {
            acc[0][j] = fmaf(q0, rv[j], acc[0][j]);
            acc[1][j] = fmaf(q1, rv[j], acc[1][j]);
        }
    }

    const float s2q = g_nq[bh * 2],            s6q = g_nq[bh * 2 + 1];
    const float s2k = g_nk[(b * KV_ + g) * 2], s6k = g_nk[(b * KV_ + g) * 2 + 1];
    const float den = s6q * s6k;
    const float scale = (den > 0.f) ? sqrtf((s2q * s2k) / den) : 0.f;

    const float* dsrc = g_dwc + (size_t)(b * N_ + n0) * 384 + g * D_;
    float* dst = g_pre + (size_t)(b * N_ + n0) * DIM_ + h * D_;
    #pragma unroll
    for (int i = 0; i < 2; i++) {
        int r = ty * 2 + i;
        #pragma unroll
        for (int j = 0; j < 6; j++) {
            int e = tx * 6 + j;
            dst[(size_t)r * DIM_ + e] =
                acc[i][j] * scale + dsrc[(size_t)r * 384 + e];
        }
    }
}

// ---------------- launch ----------------
extern "C" void kernel_launch(void* const* d_in, const int* in_sizes, int n_in,
                              void* d_out, int out_size)
{
    const float* x      = (const float*)d_in[0];
    const float* wq_w   = (const float*)d_in[1];
    const float* wq_b   = (const float*)d_in[2];
    const float* wkv_w  = (const float*)d_in[3];
    const float* wkv_b  = (const float*)d_in[4];
    const float* dwc_w  = (const float*)d_in[5];
    const float* dwc_b  = (const float*)d_in[6];
    const float* proj_w = (const float*)d_in[7];
    const float* proj_b = (const float*)d_in[8];
    float* out = (float*)d_out;

    float *gq = nullptr, *gkvp = nullptr, *gpre = nullptr;
    float *gnq = nullptr, *gnk = nullptr, *gkv = nullptr;
    cudaGetSymbolAddress((void**)&gq,   g_q);
    cudaGetSymbolAddress((void**)&gkvp, g_kvp);
    cudaGetSymbolAddress((void**)&gpre, g_pre);
    cudaGetSymbolAddress((void**)&gnq,  g_nq);
    cudaGetSymbolAddress((void**)&gnk,  g_nk);
    cudaGetSymbolAddress((void**)&gkv,  g_kv);

    cudaMemsetAsync(gnq, 0, 768 * sizeof(float));
    cudaMemsetAsync(gnk, 0, 256 * sizeof(float));
    cudaMemsetAsync(gkv, 0, 1179648 * sizeof(float));

    const int M = B_ * N_;

    tf32_gemm_bias<1><<<dim3(DIM_ / 128, M / 128), 256>>>(x, wq_w, wq_b, gq, M, DIM_, DIM_);
    tf32_gemm_bias<1><<<dim3(768  / 128, M / 128), 256>>>(x, wkv_w, wkv_b, gkvp, M, 768, DIM_);
    norm_kernel<<<dim3(B_ * H_,  8), 256>>>(0);
    norm_kernel<<<dim3(B_ * KV_, 8), 256>>>(1);
    kv_gemm_kernel<<<dim3(B_ * KV_, 8), 256>>>();
    dwc_kernel<<<dim3(32, B_), 384>>>(dwc_w, dwc_b);
    attn_kernel<<<dim3(32, B_ * H_), 256>>>();
    tf32_gemm_bias<0><<<dim3(DIM_ / 128, M / 128), 256>>>(gpre, proj_w, proj_b, out, M, DIM_, DIM_);
}

// round 5
// speedup vs baseline: 2.1424x; 1.2782x over previous
#include <cuda_runtime.h>
#include <cuda_bf16.h>
#include <cstdint>

#define B_   32
#define N_   1024
#define DIM_ 1152
#define H_   12
#define KV_  4
#define D_   96
#define MTOT (B_ * N_)        // 32768
#define KDIM 1152

// ---------------- scratch (device globals; no allocations) ----------------
__device__ float g_q[37748736];            // [B,N,1152] fp32 q
__device__ float g_kvp[25165824];          // [B,N,768] fp32 k|v
__device__ float g_dwc[12582912];          // [B,N,384]
__device__ float g_kv[1179648];            // [B,KV,96,96]
__device__ float g_nq[768];                // (s2,s6) per (b,h)
__device__ float g_nk[256];                // (s2,s6) per (b,kv)
__device__ __nv_bfloat16 g_xh[37748736];   // A hi  (x, later pre-proj)
__device__ __nv_bfloat16 g_xm[37748736];   // A mid
__device__ __nv_bfloat16 g_wqh[1327104];   // wq^T  hi  [1152][1152] (n-major, k contig)
__device__ __nv_bfloat16 g_wqm[1327104];
__device__ __nv_bfloat16 g_wkh[884736];    // wkv^T hi  [768][1152]
__device__ __nv_bfloat16 g_wkm[884736];
__device__ __nv_bfloat16 g_wph[1327104];   // proj^T hi
__device__ __nv_bfloat16 g_wpm[1327104];

// ---------------- PTX helpers ----------------
__device__ __forceinline__ void cp16(uint32_t dst, const void* src) {
    asm volatile("cp.async.ca.shared.global [%0], [%1], 16;" :: "r"(dst), "l"(src));
}
__device__ __forceinline__ void cp_commit() { asm volatile("cp.async.commit_group;"); }
template<int W> __device__ __forceinline__ void cp_wait() {
    asm volatile("cp.async.wait_group %0;" :: "n"(W));
}
__device__ __forceinline__ void mma16(float* c, const uint32_t* a, const uint32_t* b) {
    asm volatile(
        "mma.sync.aligned.m16n8k16.row.col.f32.bf16.bf16.f32 "
        "{%0,%1,%2,%3},{%4,%5,%6,%7},{%8,%9},{%0,%1,%2,%3};"
        : "+f"(c[0]), "+f"(c[1]), "+f"(c[2]), "+f"(c[3])
        : "r"(a[0]), "r"(a[1]), "r"(a[2]), "r"(a[3]), "r"(b[0]), "r"(b[1]));
}

// smem: bf16 rows padded to 40 elements (80B) — conflict-free for both
// the cp.async stores and the b32 fragment loads.
#define SSTR 40
#define TILEB 10240                       // 128 rows * 80B
#define STAGEB (4 * TILEB)                // Ah, Am, Bh, Bm
#define SMEM_TOTAL (2 * STAGEB)           // 81920

// ==== split-bf16 GEMM: C[M,Nout] = (Ah+Am)[M,K] @ (Bh+Bm)[Nout,K]^T + bias
__global__ __launch_bounds__(256) void bf16_gemm_bias(
    const __nv_bfloat16* __restrict__ Ah, const __nv_bfloat16* __restrict__ Am,
    const __nv_bfloat16* __restrict__ Bh, const __nv_bfloat16* __restrict__ Bm,
    const float* __restrict__ bias, float* __restrict__ C, int Nout)
{
    extern __shared__ __align__(128) char smem[];
    const uint32_t sb = (uint32_t)__cvta_generic_to_shared(smem);
    const int tid  = threadIdx.x;
    const int lane = tid & 31, warp = tid >> 5;
    const int wm = warp >> 2, wn = warp & 3;    // 2 x 4 warps, 64x32 each
    const int gid = lane >> 2, tig = lane & 3;

    const __nv_bfloat16* a_h = Ah + (size_t)blockIdx.y * 128 * KDIM;
    const __nv_bfloat16* a_m = Am + (size_t)blockIdx.y * 128 * KDIM;
    const __nv_bfloat16* b_h = Bh + (size_t)blockIdx.x * 128 * KDIM;
    const __nv_bfloat16* b_m = Bm + (size_t)blockIdx.x * 128 * KDIM;

    float acc[4][4][4];
    #pragma unroll
    for (int i = 0; i < 4; i++)
        #pragma unroll
        for (int j = 0; j < 4; j++)
            #pragma unroll
            for (int r = 0; r < 4; r++) acc[i][j][r] = 0.f;

    // load one K=32 stage: 4 tiles of 128 rows x 64B (4 x 16B chunks/row)
    auto load_stage = [&](int k0, int buf) {
        const uint32_t st = sb + buf * STAGEB;
        #pragma unroll
        for (int i = 0; i < 2; i++) {
            int c = tid + i * 256;           // 0..511
            int r = c >> 2, cc = c & 3;
            uint32_t so = (uint32_t)(r * 80 + cc * 16);
            size_t go = (size_t)r * KDIM + k0 + cc * 8;
            cp16(st + so,             a_h + go);
            cp16(st + TILEB + so,     a_m + go);
            cp16(st + 2 * TILEB + so, b_h + go);
            cp16(st + 3 * TILEB + so, b_m + go);
        }
        cp_commit();
    };

    const int T = KDIM / 32;                 // 36
    load_stage(0, 0);

    for (int t = 0; t < T; t++) {
        if (t + 1 < T) { load_stage((t + 1) * 32, (t + 1) & 1); cp_wait<1>(); }
        else           { cp_wait<0>(); }
        __syncthreads();

        const char* st = smem + (t & 1) * STAGEB;
        const uint32_t* sAh = (const uint32_t*)(st);
        const uint32_t* sAm = (const uint32_t*)(st + TILEB);
        const uint32_t* sBh = (const uint32_t*)(st + 2 * TILEB);
        const uint32_t* sBm = (const uint32_t*)(st + 3 * TILEB);

        #pragma unroll
        for (int ks = 0; ks < 2; ks++) {
            const int kb = ks * 8 + tig;     // b32 col
            uint32_t ah[4][4], am[4][4], bh[4][2], bm[4][2];
            #pragma unroll
            for (int ti = 0; ti < 4; ti++) {
                int r0 = (wm * 64 + ti * 16 + gid) * (SSTR / 2);
                ah[ti][0] = sAh[r0 + kb];
                ah[ti][1] = sAh[r0 + 8 * (SSTR / 2) + kb];
                ah[ti][2] = sAh[r0 + kb + 4];
                ah[ti][3] = sAh[r0 + 8 * (SSTR / 2) + kb + 4];
                am[ti][0] = sAm[r0 + kb];
                am[ti][1] = sAm[r0 + 8 * (SSTR / 2) + kb];
                am[ti][2] = sAm[r0 + kb + 4];
                am[ti][3] = sAm[r0 + 8 * (SSTR / 2) + kb + 4];
            }
            #pragma unroll
            for (int tj = 0; tj < 4; tj++) {
                int r0 = (wn * 32 + tj * 8 + gid) * (SSTR / 2);
                bh[tj][0] = sBh[r0 + kb];
                bh[tj][1] = sBh[r0 + kb + 4];
                bm[tj][0] = sBm[r0 + kb];
                bm[tj][1] = sBm[r0 + kb + 4];
            }
            #pragma unroll
            for (int ti = 0; ti < 4; ti++)
                #pragma unroll
                for (int tj = 0; tj < 4; tj++) {
                    mma16(acc[ti][tj], ah[ti], bh[tj]);
                    mma16(acc[ti][tj], ah[ti], bm[tj]);
                    mma16(acc[ti][tj], am[ti], bh[tj]);
                }
        }
        __syncthreads();
    }

    #pragma unroll
    for (int ti = 0; ti < 4; ti++) {
        #pragma unroll
        for (int tj = 0; tj < 4; tj++) {
            int row = blockIdx.y * 128 + wm * 64 + ti * 16 + gid;
            int col = blockIdx.x * 128 + wn * 32 + tj * 8 + tig * 2;
            float b0 = bias[col], b1 = bias[col + 1];
            float2 v0 = { acc[ti][tj][0] + b0, acc[ti][tj][1] + b1 };
            float2 v1 = { acc[ti][tj][2] + b0, acc[ti][tj][3] + b1 };
            *(float2*)(C + (size_t)row * Nout + col) = v0;
            *(float2*)(C + (size_t)(row + 8) * Nout + col) = v1;
        }
    }
}

// ---- split fp32 -> bf16 hi/mid ------------------------------------------
__global__ void split_kernel(const float* __restrict__ src,
                             __nv_bfloat16* __restrict__ hi,
                             __nv_bfloat16* __restrict__ mid, int n4)
{
    int i = blockIdx.x * blockDim.x + threadIdx.x;
    if (i >= n4) return;
    float4 v = ((const float4*)src)[i];
    __nv_bfloat16 h0 = __float2bfloat16(v.x), h1 = __float2bfloat16(v.y);
    __nv_bfloat16 h2 = __float2bfloat16(v.z), h3 = __float2bfloat16(v.w);
    __nv_bfloat162* hp = (__nv_bfloat162*)(hi + (size_t)i * 4);
    hp[0] = __nv_bfloat162(h0, h1);
    hp[1] = __nv_bfloat162(h2, h3);
    __nv_bfloat162* mp = (__nv_bfloat162*)(mid + (size_t)i * 4);
    mp[0] = __nv_bfloat162(__float2bfloat16(v.x - __bfloat162float(h0)),
                           __float2bfloat16(v.y - __bfloat162float(h1)));
    mp[1] = __nv_bfloat162(__float2bfloat16(v.z - __bfloat162float(h2)),
                           __float2bfloat16(v.w - __bfloat162float(h3)));
}

// ---- weight transpose + split: W[k][n] -> wT_hi/mid[n][k] ----------------
__global__ void wsplit_kernel(const float* __restrict__ W,
                              __nv_bfloat16* __restrict__ hi,
                              __nv_bfloat16* __restrict__ mid, int Nout)
{
    __shared__ float t[32][33];
    const int k0 = blockIdx.y * 32, nn0 = blockIdx.x * 32;
    const int tx = threadIdx.x, ty = threadIdx.y;
    for (int r = ty; r < 32; r += 8)
        t[r][tx] = W[(size_t)(k0 + r) * Nout + nn0 + tx];
    __syncthreads();
    for (int r = ty; r < 32; r += 8) {
        float v = t[tx][r];   // = W[k0+tx][nn0+r]
        __nv_bfloat16 h = __float2bfloat16(v);
        size_t o = (size_t)(nn0 + r) * KDIM + k0 + tx;
        hi[o] = h;
        mid[o] = __float2bfloat16(v - __bfloat162float(h));
    }
}

// ---- focus norm partials -------------------------------------------------
__global__ void norm_kernel(int which)
{
    const int nh = which ? KV_ : H_;
    const int ld = which ? 768 : DIM_;
    const float* src = which ? g_kvp : g_q;
    float* acc = which ? g_nk : g_nq;
    const int bh = blockIdx.x;
    const int b = bh / nh, hh = bh - b * nh;
    const float* base = src + (size_t)b * N_ * ld + hh * D_
                            + (size_t)blockIdx.y * 128 * ld;

    float s2 = 0.f, s6 = 0.f;
    int n = threadIdx.x / 96, d = threadIdx.x % 96;
    for (int i = threadIdx.x; i < 128 * 96; i += 256) {
        float v = fmaxf(base[(size_t)n * ld + d], 0.f);
        float v2 = v * v, v3 = v2 * v;
        s2 += v2;
        s6 += v3 * v3;
        d += 64; n += 2;
        if (d >= 96) { d -= 96; n++; }
    }
    #pragma unroll
    for (int off = 16; off; off >>= 1) {
        s2 += __shfl_xor_sync(0xffffffffu, s2, off);
        s6 += __shfl_xor_sync(0xffffffffu, s6, off);
    }
    __shared__ float w2[8], w6[8];
    const int lane = threadIdx.x & 31, warp = threadIdx.x >> 5;
    if (lane == 0) { w2[warp] = s2; w6[warp] = s6; }
    __syncthreads();
    if (threadIdx.x == 0) {
        float t2 = 0.f, t6 = 0.f;
        #pragma unroll
        for (int i = 0; i < 8; i++) { t2 += w2[i]; t6 += w6[i]; }
        atomicAdd(&acc[bh * 2], t2);
        atomicAdd(&acc[bh * 2 + 1], t6);
    }
}

// ---- kv[d,e] += sum_n relu(k[n,d])^3 * v[n,e] ----------------------------
__global__ __launch_bounds__(256) void kv_gemm_kernel()
{
    const int b = blockIdx.x >> 2;
    const int g = blockIdx.x & 3;
    __shared__ float ks[32 * 96];
    __shared__ float vs[32 * 96];
    const int tid = threadIdx.x;
    const int ty = tid >> 4, tx = tid & 15;

    float acc[6][6];
    #pragma unroll
    for (int i = 0; i < 6; i++)
        #pragma unroll
        for (int j = 0; j < 6; j++) acc[i][j] = 0.f;

    const float* kbase = g_kvp + (size_t)b * N_ * 768 + g * D_;
    const float* vbase = kbase + 384;
    const int t0b = blockIdx.y * 128;

    for (int t0 = t0b; t0 < t0b + 128; t0 += 32) {
        for (int i = tid; i < 32 * 96; i += 256) {
            int r = i / 96;
            int c = i - r * 96;
            size_t off = (size_t)(t0 + r) * 768 + c;
            float kl = fmaxf(kbase[off], 0.f);
            ks[i] = kl * kl * kl;
            vs[i] = vbase[off];
        }
        __syncthreads();
        #pragma unroll 8
        for (int kk = 0; kk < 32; kk++) {
            float rk[6], rv[6];
            #pragma unroll
            for (int i = 0; i < 6; i++) rk[i] = ks[kk * 96 + ty * 6 + i];
            #pragma unroll
            for (int j = 0; j < 6; j++) rv[j] = vs[kk * 96 + tx * 6 + j];
            #pragma unroll
            for (int i = 0; i < 6; i++)
                #pragma unroll
                for (int j = 0; j < 6; j++)
                    acc[i][j] = fmaf(rk[i], rv[j], acc[i][j]);
        }
        __syncthreads();
    }
    float* dst = g_kv + (size_t)blockIdx.x * 96 * 96;
    #pragma unroll
    for (int i = 0; i < 6; i++)
        #pragma unroll
        for (int j = 0; j < 6; j++)
            atomicAdd(&dst[(ty * 6 + i) * 96 + tx * 6 + j], acc[i][j]);
}

// ---- depthwise 3x3 conv --------------------------------------------------
__global__ __launch_bounds__(384) void dwc_kernel(const float* __restrict__ w,
                                                  const float* __restrict__ bia)
{
    const int y = blockIdx.x;
    const int b = blockIdx.y;
    const int c = threadIdx.x;

    float wr[9];
    #pragma unroll
    for (int i = 0; i < 9; i++) wr[i] = w[c * 9 + i];
    const float bv = bia[c];

    const float* base = g_kvp + (size_t)b * N_ * 768 + 384 + c;
    const float* r0 = base + (size_t)(y * 32) * 768;
    const float* rm = r0 - (size_t)32 * 768;
    const float* rp = r0 + (size_t)32 * 768;
    const bool vm = (y > 0), vp = (y < 31);

    float A0 = 0.f, A1 = 0.f, A2 = 0.f;
    float Bc0, Bc1, Bc2, Cc0, Cc1, Cc2;
    Bc0 = vm ? rm[0] : 0.f;
    Bc1 = r0[0];
    Bc2 = vp ? rp[0] : 0.f;

    float* out = g_dwc + (size_t)(b * N_ + y * 32) * 384 + c;
    for (int x = 0; x < 32; x++) {
        if (x < 31) {
            size_t o = (size_t)(x + 1) * 768;
            Cc0 = vm ? rm[o] : 0.f;
            Cc1 = r0[o];
            Cc2 = vp ? rp[o] : 0.f;
        } else {
            Cc0 = Cc1 = Cc2 = 0.f;
        }
        float o = bv;
        o = fmaf(A0, wr[0], o); o = fmaf(Bc0, wr[1], o); o = fmaf(Cc0, wr[2], o);
        o = fmaf(A1, wr[3], o); o = fmaf(Bc1, wr[4], o); o = fmaf(Cc1, wr[5], o);
        o = fmaf(A2, wr[6], o); o = fmaf(Bc2, wr[7], o); o = fmaf(Cc2, wr[8], o);
        out[(size_t)x * 384] = o;
        A0 = Bc0; A1 = Bc1; A2 = Bc2;
        Bc0 = Cc0; Bc1 = Cc1; Bc2 = Cc2;
    }
}

// ---- attn + scale + dwc fuse; writes bf16 hi/mid for proj GEMM -----------
__global__ __launch_bounds__(256) void attn_kernel()
{
    __shared__ float kvs[96 * 96];
    __shared__ float qs[32 * 96];
    const int bh = blockIdx.y;
    const int b = bh / H_;
    const int h = bh - b * H_;
    const int g = h & 3;
    const int n0 = blockIdx.x * 32;
    const int tid = threadIdx.x;

    const float* kvsrc = g_kv + (size_t)(b * KV_ + g) * 9216;
    for (int i = tid; i < 9216; i += 256) kvs[i] = kvsrc[i];

    const float* qsrc = g_q + (size_t)(b * N_ + n0) * DIM_ + h * D_;
    for (int i = tid; i < 3072; i += 256) {
        int r = i / 96;
        int d = i - r * 96;
        float v = fmaxf(qsrc[(size_t)r * DIM_ + d], 0.f);
        qs[i] = v * v * v;
    }
    __syncthreads();

    const int ty = tid >> 4, tx = tid & 15;
    float acc[2][6];
    #pragma unroll
    for (int i = 0; i < 2; i++)
        #pragma unroll
        for (int j = 0; j < 6; j++) acc[i][j] = 0.f;

    #pragma unroll 4
    for (int k = 0; k < 96; k++) {
        float q0 = qs[(ty * 2 + 0) * 96 + k];
        float q1 = qs[(ty * 2 + 1) * 96 + k];
        float rv[6];
        #pragma unroll
        for (int j = 0; j < 6; j++) rv[j] = kvs[k * 96 + tx * 6 + j];
        #pragma unroll
        for (int j = 0; j < 6; j++) {
            acc[0][j] = fmaf(q0, rv[j], acc[0][j]);
            acc[1][j] = fmaf(q1, rv[j], acc[1][j]);
        }
    }

    const float s2q = g_nq[bh * 2],            s6q = g_nq[bh * 2 + 1];
    const float s2k = g_nk[(b * KV_ + g) * 2], s6k = g_nk[(b * KV_ + g) * 2 + 1];
    const float den = s6q * s6k;
    const float scale = (den > 0.f) ? sqrtf((s2q * s2k) / den) : 0.f;

    const float* dsrc = g_dwc + (size_t)(b * N_ + n0) * 384 + g * D_;
    #pragma unroll
    for (int i = 0; i < 2; i++) {
        int r = ty * 2 + i;
        size_t rowbase = (size_t)(b * N_ + n0 + r) * DIM_ + h * D_;
        #pragma unroll
        for (int j = 0; j < 6; j++) {
            int e = tx * 6 + j;
            float val = acc[i][j] * scale + dsrc[(size_t)r * 384 + e];
            __nv_bfloat16 hh = __float2bfloat16(val);
            g_xh[rowbase + e] = hh;
            g_xm[rowbase + e] = __float2bfloat16(val - __bfloat162float(hh));
        }
    }
}

// ---------------- launch ----------------
extern "C" void kernel_launch(void* const* d_in, const int* in_sizes, int n_in,
                              void* d_out, int out_size)
{
    const float* x      = (const float*)d_in[0];
    const float* wq_w   = (const float*)d_in[1];
    const float* wq_b   = (const float*)d_in[2];
    const float* wkv_w  = (const float*)d_in[3];
    const float* wkv_b  = (const float*)d_in[4];
    const float* dwc_w  = (const float*)d_in[5];
    const float* dwc_b  = (const float*)d_in[6];
    const float* proj_w = (const float*)d_in[7];
    const float* proj_b = (const float*)d_in[8];
    float* out = (float*)d_out;

    cudaFuncSetAttribute(bf16_gemm_bias,
                         cudaFuncAttributeMaxDynamicSharedMemorySize, SMEM_TOTAL);

    float *gq, *gkvp, *gnq, *gnk, *gkv;
    __nv_bfloat16 *xh, *xm, *wqh, *wqm, *wkh, *wkm, *wph, *wpm;
    cudaGetSymbolAddress((void**)&gq,   g_q);
    cudaGetSymbolAddress((void**)&gkvp, g_kvp);
    cudaGetSymbolAddress((void**)&gnq,  g_nq);
    cudaGetSymbolAddress((void**)&gnk,  g_nk);
    cudaGetSymbolAddress((void**)&gkv,  g_kv);
    cudaGetSymbolAddress((void**)&xh,   g_xh);
    cudaGetSymbolAddress((void**)&xm,   g_xm);
    cudaGetSymbolAddress((void**)&wqh,  g_wqh);
    cudaGetSymbolAddress((void**)&wqm,  g_wqm);
    cudaGetSymbolAddress((void**)&wkh,  g_wkh);
    cudaGetSymbolAddress((void**)&wkm,  g_wkm);
    cudaGetSymbolAddress((void**)&wph,  g_wph);
    cudaGetSymbolAddress((void**)&wpm,  g_wpm);

    cudaMemsetAsync(gnq, 0, 768 * sizeof(float));
    cudaMemsetAsync(gnk, 0, 256 * sizeof(float));
    cudaMemsetAsync(gkv, 0, 1179648 * sizeof(float));

    // prep: splits + weight transposes
    split_kernel<<<(MTOT * DIM_ / 4 + 255) / 256, 256>>>(x, xh, xm, MTOT * DIM_ / 4);
    wsplit_kernel<<<dim3(DIM_ / 32, KDIM / 32), dim3(32, 8)>>>(wq_w, wqh, wqm, DIM_);
    wsplit_kernel<<<dim3(768  / 32, KDIM / 32), dim3(32, 8)>>>(wkv_w, wkh, wkm, 768);
    wsplit_kernel<<<dim3(DIM_ / 32, KDIM / 32), dim3(32, 8)>>>(proj_w, wph, wpm, DIM_);

    // q and kv projections (tensor cores, split-bf16)
    bf16_gemm_bias<<<dim3(DIM_ / 128, MTOT / 128), 256, SMEM_TOTAL>>>(
        xh, xm, wqh, wqm, wq_b, gq, DIM_);
    bf16_gemm_bias<<<dim3(768 / 128, MTOT / 128), 256, SMEM_TOTAL>>>(
        xh, xm, wkh, wkm, wkv_b, gkvp, 768);

    norm_kernel<<<dim3(B_ * H_,  8), 256>>>(0);
    norm_kernel<<<dim3(B_ * KV_, 8), 256>>>(1);
    kv_gemm_kernel<<<dim3(B_ * KV_, 8), 256>>>();
    dwc_kernel<<<dim3(32, B_), 384>>>(dwc_w, dwc_b);
    attn_kernel<<<dim3(32, B_ * H_), 256>>>();   // writes xh/xm (pre-proj)

    // out projection
    bf16_gemm_bias<<<dim3(DIM_ / 128, MTOT / 128), 256, SMEM_TOTAL>>>(
        xh, xm, wph, wpm, proj_b, out, DIM_);
}